// round 1
// baseline (speedup 1.0000x reference)
#include <cuda_runtime.h>
#include <cuda_bf16.h>

#define T_LEN 500
#define S_SIMS 4096
#define D_DIM 6
#define A_DIM 3
#define H_DIM 64
#define ALPHA_C 0.1f
#define BLOCK_THREADS 128
#define EPT 4   // elements (t-slots) per thread

// scratch for per-simulation partial products (device global: allocation-free)
__device__ float g_partial[S_SIMS];

__global__ __launch_bounds__(BLOCK_THREADS) void mepg_main(
    const float* __restrict__ st,   // [S, D, T]
    const float* __restrict__ at,   // [S, A, T]
    const float* __restrict__ rw,   // [S, T]
    const float* __restrict__ pW1,  // [H, D]
    const float* __restrict__ pb1,  // [H]
    const float* __restrict__ pW2,  // [A, H]
    const float* __restrict__ pb2,  // [A]
    const float* __restrict__ bW1,  // [H, D]
    const float* __restrict__ bb1,  // [H]
    const float* __restrict__ bW2,  // [1, H]
    const float* __restrict__ bb2,  // [1]
    const float* __restrict__ sd)   // [A, A]
{
    __shared__ float4 sW1p[H_DIM * 2];  // policy W1 rows padded to 8 floats
    __shared__ float4 sW1b[H_DIM * 2];  // baseline W1 rows padded to 8 floats
    __shared__ float4 sComb[H_DIM];     // {pW2[0][j], pW2[1][j], pW2[2][j], bW2[j]}
    __shared__ float2 sBias[H_DIM];     // {pb1[j], bb1[j]}
    __shared__ float  sRedA[BLOCK_THREADS / 32];
    __shared__ float  sRedB[BLOCK_THREADS / 32];

    const int tid = threadIdx.x;
    const int s   = blockIdx.x;

    // ---- stage weights into shared memory ----
    for (int j = tid; j < H_DIM; j += BLOCK_THREADS) {
        const float* r  = pW1 + j * D_DIM;
        const float* rb = bW1 + j * D_DIM;
        sW1p[2 * j]     = make_float4(r[0], r[1], r[2], r[3]);
        sW1p[2 * j + 1] = make_float4(r[4], r[5], 0.f, 0.f);
        sW1b[2 * j]     = make_float4(rb[0], rb[1], rb[2], rb[3]);
        sW1b[2 * j + 1] = make_float4(rb[4], rb[5], 0.f, 0.f);
        sComb[j] = make_float4(pW2[0 * H_DIM + j], pW2[1 * H_DIM + j],
                               pW2[2 * H_DIM + j], bW2[j]);
        sBias[j] = make_float2(pb1[j], bb1[j]);
    }
    __syncthreads();

    // ---- 3x3 Cholesky of sd and lower-triangular inverse (per thread, cheap) ----
    const float L00 = sqrtf(sd[0]);
    const float L10 = sd[3] / L00;
    const float L11 = sqrtf(sd[4] - L10 * L10);
    const float L20 = sd[6] / L00;
    const float L21 = (sd[7] - L20 * L10) / L11;
    const float L22 = sqrtf(sd[8] - L20 * L20 - L21 * L21);
    const float Li00 = 1.0f / L00;
    const float Li11 = 1.0f / L11;
    const float Li22 = 1.0f / L22;
    const float Li10 = -L10 * Li00 * Li11;
    const float Li21 = -L21 * Li11 * Li22;
    const float Li20 = (L10 * L21 - L20 * L11) * (Li00 * Li11 * Li22);
    // -(sum log diag L) - 0.5 * A * log(2*pi)
    const float cterm = -(logf(L00) + logf(L11) + logf(L22))
                        - 0.5f * 3.0f * 1.8378770664093453f;

    const float pb2_0 = pb2[0], pb2_1 = pb2[1], pb2_2 = pb2[2];
    const float bb2_0 = bb2[0];

    const float* stS = st + (size_t)s * D_DIM * T_LEN;
    const float* atS = at + (size_t)s * A_DIM * T_LEN;
    const float* rwS = rw + (size_t)s * T_LEN;

    // ---- load this thread's EPT elements (coalesced in t) ----
    float x[EPT][D_DIM];
    float av[EPT][A_DIM];
    float rv[EPT];
    bool  valid[EPT];
    int   tt[EPT];
#pragma unroll
    for (int k = 0; k < EPT; k++) {
        int t = tid + k * BLOCK_THREADS;
        tt[k] = t;
        bool v = (t < T_LEN);
        valid[k] = v;
        int tc = v ? t : 0;
#pragma unroll
        for (int d = 0; d < D_DIM; d++) x[k][d] = stS[d * T_LEN + tc];
#pragma unroll
        for (int i = 0; i < A_DIM; i++) av[k][i] = atS[i * T_LEN + tc];
        rv[k] = rwS[tc];
    }

    // ---- fused policy + baseline MLP over hidden dim ----
    float m0[EPT], m1[EPT], m2[EPT], bl[EPT];
#pragma unroll
    for (int k = 0; k < EPT; k++) {
        m0[k] = pb2_0; m1[k] = pb2_1; m2[k] = pb2_2; bl[k] = bb2_0;
    }

#pragma unroll 4
    for (int j = 0; j < H_DIM; j++) {
        const float4 wa = sW1p[2 * j];
        const float4 wb = sW1p[2 * j + 1];
        const float4 va = sW1b[2 * j];
        const float4 vb = sW1b[2 * j + 1];
        const float4 c  = sComb[j];
        const float2 bi = sBias[j];
#pragma unroll
        for (int k = 0; k < EPT; k++) {
            float hp = bi.x;
            hp = fmaf(x[k][0], wa.x, hp);
            hp = fmaf(x[k][1], wa.y, hp);
            hp = fmaf(x[k][2], wa.z, hp);
            hp = fmaf(x[k][3], wa.w, hp);
            hp = fmaf(x[k][4], wb.x, hp);
            hp = fmaf(x[k][5], wb.y, hp);
            float hb = bi.y;
            hb = fmaf(x[k][0], va.x, hb);
            hb = fmaf(x[k][1], va.y, hb);
            hb = fmaf(x[k][2], va.z, hb);
            hb = fmaf(x[k][3], va.w, hb);
            hb = fmaf(x[k][4], vb.x, hb);
            hb = fmaf(x[k][5], vb.y, hb);
            hp = fmaxf(hp, 0.0f);
            hb = fmaxf(hb, 0.0f);
            m0[k] = fmaf(hp, c.x, m0[k]);
            m1[k] = fmaf(hp, c.y, m1[k]);
            m2[k] = fmaf(hp, c.z, m2[k]);
            bl[k] = fmaf(hb, c.w, bl[k]);
        }
    }

    // ---- log-likelihood + streaming per-s sums ----
    float SA = 0.0f, SL = 0.0f;
#pragma unroll
    for (int k = 0; k < EPT; k++) {
        if (valid[k]) {
            float d0 = av[k][0] - m0[k];
            float d1 = av[k][1] - m1[k];
            float d2 = av[k][2] - m2[k];
            float z0 = Li00 * d0;
            float z1 = fmaf(Li10, d0, Li11 * d1);
            float z2 = fmaf(Li20, d0, fmaf(Li21, d1, Li22 * d2));
            float ll = fmaf(-0.5f, fmaf(z0, z0, fmaf(z1, z1, z2 * z2)), cterm);
            float g  = __expf(rv[k]) - ALPHA_C * ll;
            // sum_t cum[t] = sum_t (t+1)*g[t]; subtract baseline sum
            SA = fmaf((float)(tt[k] + 1), g, SA) - bl[k];
            SL += ll;
        }
    }

    // ---- block reduction (warp shuffle + smem) ----
    const int lane = tid & 31;
    const int warp = tid >> 5;
#pragma unroll
    for (int o = 16; o > 0; o >>= 1) {
        SA += __shfl_down_sync(0xffffffffu, SA, o);
        SL += __shfl_down_sync(0xffffffffu, SL, o);
    }
    if (lane == 0) { sRedA[warp] = SA; sRedB[warp] = SL; }
    __syncthreads();
    if (tid == 0) {
        float a = 0.0f, b = 0.0f;
#pragma unroll
        for (int w = 0; w < BLOCK_THREADS / 32; w++) { a += sRedA[w]; b += sRedB[w]; }
        g_partial[s] = a * b;
    }
}

__global__ void mepg_reduce(float* __restrict__ out) {
    __shared__ float sh[256];
    int tid = threadIdx.x;
    float v = 0.0f;
    for (int i = tid; i < S_SIMS; i += 256) v += g_partial[i];
    sh[tid] = v;
    __syncthreads();
    for (int stp = 128; stp > 0; stp >>= 1) {
        if (tid < stp) sh[tid] += sh[tid + stp];
        __syncthreads();
    }
    if (tid == 0) out[0] = sh[0] * (1.0f / ((float)T_LEN * (float)S_SIMS));
}

extern "C" void kernel_launch(void* const* d_in, const int* in_sizes, int n_in,
                              void* d_out, int out_size) {
    const float* st  = (const float*)d_in[0];
    const float* at  = (const float*)d_in[1];
    const float* rw  = (const float*)d_in[2];
    const float* pW1 = (const float*)d_in[3];
    const float* pb1 = (const float*)d_in[4];
    const float* pW2 = (const float*)d_in[5];
    const float* pb2 = (const float*)d_in[6];
    const float* bW1 = (const float*)d_in[7];
    const float* bb1 = (const float*)d_in[8];
    const float* bW2 = (const float*)d_in[9];
    const float* bb2 = (const float*)d_in[10];
    const float* sd  = (const float*)d_in[11];
    float* out = (float*)d_out;

    mepg_main<<<S_SIMS, BLOCK_THREADS>>>(st, at, rw, pW1, pb1, pW2, pb2,
                                         bW1, bb1, bW2, bb2, sd);
    mepg_reduce<<<1, 256>>>(out);
}

// round 2
// speedup vs baseline: 1.0028x; 1.0028x over previous
#include <cuda_runtime.h>
#include <cuda_bf16.h>

#define T_LEN 500
#define S_SIMS 4096
#define D_DIM 6
#define A_DIM 3
#define H_DIM 64
#define JP    (H_DIM / 2)     // 32 hidden-unit pairs
#define ALPHA_C 0.1f
#define BLOCK_THREADS 256
#define EPT 2                 // t-slots per thread (256*2 = 512 >= 500)

__device__ float g_partial[S_SIMS];
__device__ int   g_count = 0;

// ---- packed f32x2 helpers (Blackwell-only, PTX-reachable) ----
__device__ __forceinline__ unsigned long long pk2(float a, float b) {
    unsigned long long r;
    asm("mov.b64 %0, {%1, %2};" : "=l"(r) : "f"(a), "f"(b));
    return r;
}
__device__ __forceinline__ void upk2(unsigned long long v, float& a, float& b) {
    asm("mov.b64 {%0, %1}, %2;" : "=f"(a), "=f"(b) : "l"(v));
}
__device__ __forceinline__ unsigned long long fma2(unsigned long long a,
                                                   unsigned long long b,
                                                   unsigned long long c) {
    unsigned long long d;
    asm("fma.rn.f32x2 %0, %1, %2, %3;" : "=l"(d) : "l"(a), "l"(b), "l"(c));
    return d;
}
__device__ __forceinline__ unsigned long long relu2(unsigned long long v) {
    float a, b;
    upk2(v, a, b);
    return pk2(fmaxf(a, 0.0f), fmaxf(b, 0.0f));
}

__global__ __launch_bounds__(BLOCK_THREADS) void mepg_main(
    const float* __restrict__ st,   // [S, D, T]
    const float* __restrict__ at,   // [S, A, T]
    const float* __restrict__ rw,   // [S, T]
    const float* __restrict__ pW1,  // [H, D]
    const float* __restrict__ pb1,  // [H]
    const float* __restrict__ pW2,  // [A, H]
    const float* __restrict__ pb2,  // [A]
    const float* __restrict__ bW1,  // [H, D]
    const float* __restrict__ bb1,  // [H]
    const float* __restrict__ bW2,  // [1, H]
    const float* __restrict__ bb2,  // [1]
    const float* __restrict__ sd,   // [A, A]
    float* __restrict__ out)
{
    // hidden-unit-pair packed weights: lane0 = unit 2*jp, lane1 = unit 2*jp+1
    __shared__ float2 sW1p[JP * D_DIM];   // policy W1 pairs
    __shared__ float2 sW1b[JP * D_DIM];   // baseline W1 pairs
    __shared__ float2 sC[JP * 4];         // {pW2 row0, row1, row2, bW2} pairs
    __shared__ float2 sB[JP * 2];         // {pb1 pair, bb1 pair}
    __shared__ float  sRedA[BLOCK_THREADS / 32];
    __shared__ float  sRedB[BLOCK_THREADS / 32];
    __shared__ int    sIsLast;

    const int tid = threadIdx.x;
    const int s   = blockIdx.x;

    for (int jp = tid; jp < JP; jp += BLOCK_THREADS) {
        const int j0 = 2 * jp, j1 = j0 + 1;
#pragma unroll
        for (int d = 0; d < D_DIM; d++) {
            sW1p[jp * D_DIM + d] = make_float2(pW1[j0 * D_DIM + d], pW1[j1 * D_DIM + d]);
            sW1b[jp * D_DIM + d] = make_float2(bW1[j0 * D_DIM + d], bW1[j1 * D_DIM + d]);
        }
        sC[jp * 4 + 0] = make_float2(pW2[0 * H_DIM + j0], pW2[0 * H_DIM + j1]);
        sC[jp * 4 + 1] = make_float2(pW2[1 * H_DIM + j0], pW2[1 * H_DIM + j1]);
        sC[jp * 4 + 2] = make_float2(pW2[2 * H_DIM + j0], pW2[2 * H_DIM + j1]);
        sC[jp * 4 + 3] = make_float2(bW2[j0], bW2[j1]);
        sB[jp * 2 + 0] = make_float2(pb1[j0], pb1[j1]);
        sB[jp * 2 + 1] = make_float2(bb1[j0], bb1[j1]);
    }
    __syncthreads();

    // ---- 3x3 Cholesky of sd + lower-triangular inverse (cheap, per thread) ----
    const float L00 = sqrtf(sd[0]);
    const float L10 = sd[3] / L00;
    const float L11 = sqrtf(sd[4] - L10 * L10);
    const float L20 = sd[6] / L00;
    const float L21 = (sd[7] - L20 * L10) / L11;
    const float L22 = sqrtf(sd[8] - L20 * L20 - L21 * L21);
    const float Li00 = 1.0f / L00;
    const float Li11 = 1.0f / L11;
    const float Li22 = 1.0f / L22;
    const float Li10 = -L10 * Li00 * Li11;
    const float Li21 = -L21 * Li11 * Li22;
    const float Li20 = (L10 * L21 - L20 * L11) * (Li00 * Li11 * Li22);
    const float cterm = -(logf(L00) + logf(L11) + logf(L22))
                        - 0.5f * 3.0f * 1.8378770664093453f;

    const float* stS = st + (size_t)s * D_DIM * T_LEN;
    const float* atS = at + (size_t)s * A_DIM * T_LEN;
    const float* rwS = rw + (size_t)s * T_LEN;

    // ---- per-thread elements (coalesced in t), duplicated into f32x2 lanes ----
    unsigned long long x2[EPT][D_DIM];
    float av[EPT][A_DIM];
    float rv[EPT];
    bool  valid[EPT];
    int   tt[EPT];
#pragma unroll
    for (int k = 0; k < EPT; k++) {
        const int t = tid + k * BLOCK_THREADS;
        tt[k] = t;
        const bool v = (t < T_LEN);
        valid[k] = v;
        const int tc = v ? t : 0;
#pragma unroll
        for (int d = 0; d < D_DIM; d++) {
            const float xv = stS[d * T_LEN + tc];
            x2[k][d] = pk2(xv, xv);
        }
#pragma unroll
        for (int i = 0; i < A_DIM; i++) av[k][i] = atS[i * T_LEN + tc];
        rv[k] = rwS[tc];
    }

    // ---- packed accumulators: lane-wise partial output sums ----
    unsigned long long m0a[EPT], m1a[EPT], m2a[EPT], bla[EPT];
#pragma unroll
    for (int k = 0; k < EPT; k++) {
        m0a[k] = pk2(pb2[0], 0.0f);
        m1a[k] = pk2(pb2[1], 0.0f);
        m2a[k] = pk2(pb2[2], 0.0f);
        bla[k] = pk2(bb2[0], 0.0f);
    }

#pragma unroll 2
    for (int jp = 0; jp < JP; jp++) {
        unsigned long long wp[D_DIM], wb[D_DIM];
#pragma unroll
        for (int d = 0; d < D_DIM; d++) {
            const float2 a = sW1p[jp * D_DIM + d];
            const float2 b = sW1b[jp * D_DIM + d];
            wp[d] = pk2(a.x, a.y);
            wb[d] = pk2(b.x, b.y);
        }
        const float2 c0f = sC[jp * 4 + 0];
        const float2 c1f = sC[jp * 4 + 1];
        const float2 c2f = sC[jp * 4 + 2];
        const float2 cbf = sC[jp * 4 + 3];
        const unsigned long long c0 = pk2(c0f.x, c0f.y);
        const unsigned long long c1 = pk2(c1f.x, c1f.y);
        const unsigned long long c2 = pk2(c2f.x, c2f.y);
        const unsigned long long cb = pk2(cbf.x, cbf.y);
        const float2 bpf = sB[jp * 2 + 0];
        const float2 bbf = sB[jp * 2 + 1];
        const unsigned long long bp = pk2(bpf.x, bpf.y);
        const unsigned long long bb = pk2(bbf.x, bbf.y);

#pragma unroll
        for (int k = 0; k < EPT; k++) {
            unsigned long long hp = bp;
            unsigned long long hb = bb;
#pragma unroll
            for (int d = 0; d < D_DIM; d++) {
                hp = fma2(x2[k][d], wp[d], hp);
                hb = fma2(x2[k][d], wb[d], hb);
            }
            hp = relu2(hp);
            hb = relu2(hb);
            m0a[k] = fma2(hp, c0, m0a[k]);
            m1a[k] = fma2(hp, c1, m1a[k]);
            m2a[k] = fma2(hp, c2, m2a[k]);
            bla[k] = fma2(hb, cb, bla[k]);
        }
    }

    // ---- collapse lanes, log-likelihood, streaming per-s sums ----
    float SA = 0.0f, SL = 0.0f;
#pragma unroll
    for (int k = 0; k < EPT; k++) {
        if (valid[k]) {
            float lo, hi;
            upk2(m0a[k], lo, hi); const float m0 = lo + hi;
            upk2(m1a[k], lo, hi); const float m1 = lo + hi;
            upk2(m2a[k], lo, hi); const float m2 = lo + hi;
            upk2(bla[k], lo, hi); const float bl = lo + hi;
            const float d0 = av[k][0] - m0;
            const float d1 = av[k][1] - m1;
            const float d2 = av[k][2] - m2;
            const float z0 = Li00 * d0;
            const float z1 = fmaf(Li10, d0, Li11 * d1);
            const float z2 = fmaf(Li20, d0, fmaf(Li21, d1, Li22 * d2));
            const float ll = fmaf(-0.5f, fmaf(z0, z0, fmaf(z1, z1, z2 * z2)), cterm);
            const float g  = __expf(rv[k]) - ALPHA_C * ll;
            SA = fmaf((float)(tt[k] + 1), g, SA) - bl;
            SL += ll;
        }
    }

    // ---- block reduction ----
    const int lane = tid & 31;
    const int warp = tid >> 5;
#pragma unroll
    for (int o = 16; o > 0; o >>= 1) {
        SA += __shfl_down_sync(0xffffffffu, SA, o);
        SL += __shfl_down_sync(0xffffffffu, SL, o);
    }
    if (lane == 0) { sRedA[warp] = SA; sRedB[warp] = SL; }
    __syncthreads();
    if (tid == 0) {
        float a = 0.0f, b = 0.0f;
#pragma unroll
        for (int w = 0; w < BLOCK_THREADS / 32; w++) { a += sRedA[w]; b += sRedB[w]; }
        g_partial[s] = a * b;
        __threadfence();
        const int c = atomicAdd(&g_count, 1);
        sIsLast = (c == gridDim.x - 1) ? 1 : 0;
    }
    __syncthreads();

    // ---- last block folds the final reduction (deterministic fixed order) ----
    if (sIsLast) {
        float v = 0.0f;
        for (int i = tid; i < S_SIMS; i += BLOCK_THREADS) v += __ldcg(&g_partial[i]);
#pragma unroll
        for (int o = 16; o > 0; o >>= 1) v += __shfl_down_sync(0xffffffffu, v, o);
        if (lane == 0) sRedA[warp] = v;
        __syncthreads();
        if (tid == 0) {
            float tot = 0.0f;
#pragma unroll
            for (int w = 0; w < BLOCK_THREADS / 32; w++) tot += sRedA[w];
            out[0] = tot * (1.0f / ((float)T_LEN * (float)S_SIMS));
            g_count = 0;   // reset for next graph replay
        }
    }
}

extern "C" void kernel_launch(void* const* d_in, const int* in_sizes, int n_in,
                              void* d_out, int out_size) {
    const float* st  = (const float*)d_in[0];
    const float* at  = (const float*)d_in[1];
    const float* rw  = (const float*)d_in[2];
    const float* pW1 = (const float*)d_in[3];
    const float* pb1 = (const float*)d_in[4];
    const float* pW2 = (const float*)d_in[5];
    const float* pb2 = (const float*)d_in[6];
    const float* bW1 = (const float*)d_in[7];
    const float* bb1 = (const float*)d_in[8];
    const float* bW2 = (const float*)d_in[9];
    const float* bb2 = (const float*)d_in[10];
    const float* sd  = (const float*)d_in[11];
    float* out = (float*)d_out;

    mepg_main<<<S_SIMS, BLOCK_THREADS>>>(st, at, rw, pW1, pb1, pW2, pb2,
                                         bW1, bb1, bW2, bb2, sd, out);
}

// round 3
// speedup vs baseline: 1.1257x; 1.1226x over previous
#include <cuda_runtime.h>
#include <cuda_bf16.h>

#define T_LEN 500
#define S_SIMS 4096
#define D_DIM 6
#define A_DIM 3
#define H_DIM 64
#define JP    (H_DIM / 2)     // 32 hidden-unit pairs
#define ALPHA_C 0.1f
#define BLOCK_THREADS 128
#define EPT 4                 // 128*4 = 512 >= 500 t-slots

__device__ float g_partial[S_SIMS];
__device__ int   g_count = 0;

// ---- packed f32x2 helpers ----
__device__ __forceinline__ unsigned long long pk2(float a, float b) {
    unsigned long long r;
    asm("mov.b64 %0, {%1, %2};" : "=l"(r) : "f"(a), "f"(b));
    return r;
}
__device__ __forceinline__ void upk2(unsigned long long v, float& a, float& b) {
    asm("mov.b64 {%0, %1}, %2;" : "=f"(a), "=f"(b) : "l"(v));
}
__device__ __forceinline__ unsigned long long fma2(unsigned long long a,
                                                   unsigned long long b,
                                                   unsigned long long c) {
    unsigned long long d;
    asm("fma.rn.f32x2 %0, %1, %2, %3;" : "=l"(d) : "l"(a), "l"(b), "l"(c));
    return d;
}
__device__ __forceinline__ unsigned long long relu2(unsigned long long v) {
    float a, b;
    upk2(v, a, b);
    return pk2(fmaxf(a, 0.0f), fmaxf(b, 0.0f));
}

__global__ __launch_bounds__(BLOCK_THREADS, 4) void mepg_main(
    const float* __restrict__ st,   // [S, D, T]
    const float* __restrict__ at,   // [S, A, T]
    const float* __restrict__ rw,   // [S, T]
    const float* __restrict__ pW1,  // [H, D]
    const float* __restrict__ pb1,  // [H]
    const float* __restrict__ pW2,  // [A, H]
    const float* __restrict__ pb2,  // [A]
    const float* __restrict__ bW1,  // [H, D]
    const float* __restrict__ bb1,  // [H]
    const float* __restrict__ bW2,  // [1, H]
    const float* __restrict__ bb2,  // [1]
    const float* __restrict__ sd,   // [A, A]
    float* __restrict__ out)
{
    // 16B-packed weight pairs: one LDS.128 = two fma2 operands, no repack MOVs.
    // sWW[jp*6+d] = { {pW1[j0][d],pW1[j1][d]} , {bW1[j0][d],bW1[j1][d]} }
    __shared__ ulonglong2 sWW[JP * D_DIM];
    // sCC[2*jp+0] = { c0 pair, c1 pair }, sCC[2*jp+1] = { c2 pair, bW2 pair }
    __shared__ ulonglong2 sCC[JP * 2];
    // sBB[jp] = { pb1 pair, bb1 pair }
    __shared__ ulonglong2 sBB[JP];
    __shared__ float sRedA[BLOCK_THREADS / 32];
    __shared__ float sRedB[BLOCK_THREADS / 32];
    __shared__ int   sIsLast;

    const int tid = threadIdx.x;
    const int s   = blockIdx.x;

    for (int jp = tid; jp < JP; jp += BLOCK_THREADS) {
        const int j0 = 2 * jp, j1 = j0 + 1;
#pragma unroll
        for (int d = 0; d < D_DIM; d++) {
            sWW[jp * D_DIM + d].x = pk2(pW1[j0 * D_DIM + d], pW1[j1 * D_DIM + d]);
            sWW[jp * D_DIM + d].y = pk2(bW1[j0 * D_DIM + d], bW1[j1 * D_DIM + d]);
        }
        sCC[2 * jp + 0].x = pk2(pW2[0 * H_DIM + j0], pW2[0 * H_DIM + j1]);
        sCC[2 * jp + 0].y = pk2(pW2[1 * H_DIM + j0], pW2[1 * H_DIM + j1]);
        sCC[2 * jp + 1].x = pk2(pW2[2 * H_DIM + j0], pW2[2 * H_DIM + j1]);
        sCC[2 * jp + 1].y = pk2(bW2[j0], bW2[j1]);
        sBB[jp].x = pk2(pb1[j0], pb1[j1]);
        sBB[jp].y = pk2(bb1[j0], bb1[j1]);
    }
    __syncthreads();

    const float* stS = st + (size_t)s * D_DIM * T_LEN;
    const float* atS = at + (size_t)s * A_DIM * T_LEN;
    const float* rwS = rw + (size_t)s * T_LEN;

    // ---- load state (coalesced in t), duplicate into both f32x2 lanes ----
    unsigned long long x2[EPT][D_DIM];
    int tt[EPT];
#pragma unroll
    for (int k = 0; k < EPT; k++) {
        const int t = tid + k * BLOCK_THREADS;
        tt[k] = t;
        const int tc = (t < T_LEN) ? t : 0;
#pragma unroll
        for (int d = 0; d < D_DIM; d++) {
            const float xv = stS[d * T_LEN + tc];
            x2[k][d] = pk2(xv, xv);
        }
    }

    // ---- packed accumulators (lane-wise partial output sums) ----
    const float pb20 = pb2[0], pb21 = pb2[1], pb22 = pb2[2], bb20 = bb2[0];
    unsigned long long m0a[EPT], m1a[EPT], m2a[EPT], bla[EPT];
#pragma unroll
    for (int k = 0; k < EPT; k++) {
        m0a[k] = pk2(pb20, 0.0f);
        m1a[k] = pk2(pb21, 0.0f);
        m2a[k] = pk2(pb22, 0.0f);
        bla[k] = pk2(bb20, 0.0f);
    }

#pragma unroll 2
    for (int jp = 0; jp < JP; jp++) {
        ulonglong2 w[D_DIM];
#pragma unroll
        for (int d = 0; d < D_DIM; d++) w[d] = sWW[jp * D_DIM + d];
        const ulonglong2 cA = sCC[2 * jp + 0];
        const ulonglong2 cB = sCC[2 * jp + 1];
        const ulonglong2 bi = sBB[jp];

#pragma unroll
        for (int k = 0; k < EPT; k++) {
            unsigned long long hp = bi.x;
            unsigned long long hb = bi.y;
#pragma unroll
            for (int d = 0; d < D_DIM; d++) {
                hp = fma2(x2[k][d], w[d].x, hp);
                hb = fma2(x2[k][d], w[d].y, hb);
            }
            hp = relu2(hp);
            hb = relu2(hb);
            m0a[k] = fma2(hp, cA.x, m0a[k]);
            m1a[k] = fma2(hp, cA.y, m1a[k]);
            m2a[k] = fma2(hp, cB.x, m2a[k]);
            bla[k] = fma2(hb, cB.y, bla[k]);
        }
    }

    // ---- Cholesky terms (cheap, after the hot loop) ----
    const float L00 = sqrtf(sd[0]);
    const float L10 = sd[3] / L00;
    const float L11 = sqrtf(sd[4] - L10 * L10);
    const float L20 = sd[6] / L00;
    const float L21 = (sd[7] - L20 * L10) / L11;
    const float L22 = sqrtf(sd[8] - L20 * L20 - L21 * L21);
    const float Li00 = 1.0f / L00;
    const float Li11 = 1.0f / L11;
    const float Li22 = 1.0f / L22;
    const float Li10 = -L10 * Li00 * Li11;
    const float Li21 = -L21 * Li11 * Li22;
    const float Li20 = (L10 * L21 - L20 * L11) * (Li00 * Li11 * Li22);
    const float cterm = -(logf(L00) + logf(L11) + logf(L22))
                        - 0.5f * 3.0f * 1.8378770664093453f;

    // ---- actions/rewards loaded here (keeps hot-loop register pressure low) ----
    float SA = 0.0f, SL = 0.0f;
#pragma unroll
    for (int k = 0; k < EPT; k++) {
        const int t = tt[k];
        if (t < T_LEN) {
            const float a0 = atS[0 * T_LEN + t];
            const float a1 = atS[1 * T_LEN + t];
            const float a2 = atS[2 * T_LEN + t];
            const float rvv = rwS[t];
            float lo, hi;
            upk2(m0a[k], lo, hi); const float m0 = lo + hi;
            upk2(m1a[k], lo, hi); const float m1 = lo + hi;
            upk2(m2a[k], lo, hi); const float m2 = lo + hi;
            upk2(bla[k], lo, hi); const float bl = lo + hi;
            const float d0 = a0 - m0;
            const float d1 = a1 - m1;
            const float d2 = a2 - m2;
            const float z0 = Li00 * d0;
            const float z1 = fmaf(Li10, d0, Li11 * d1);
            const float z2 = fmaf(Li20, d0, fmaf(Li21, d1, Li22 * d2));
            const float ll = fmaf(-0.5f, fmaf(z0, z0, fmaf(z1, z1, z2 * z2)), cterm);
            const float g  = __expf(rvv) - ALPHA_C * ll;
            SA = fmaf((float)(t + 1), g, SA) - bl;
            SL += ll;
        }
    }

    // ---- block reduction ----
    const int lane = tid & 31;
    const int warp = tid >> 5;
#pragma unroll
    for (int o = 16; o > 0; o >>= 1) {
        SA += __shfl_down_sync(0xffffffffu, SA, o);
        SL += __shfl_down_sync(0xffffffffu, SL, o);
    }
    if (lane == 0) { sRedA[warp] = SA; sRedB[warp] = SL; }
    __syncthreads();
    if (tid == 0) {
        float a = 0.0f, b = 0.0f;
#pragma unroll
        for (int w = 0; w < BLOCK_THREADS / 32; w++) { a += sRedA[w]; b += sRedB[w]; }
        g_partial[s] = a * b;
        __threadfence();
        const int c = atomicAdd(&g_count, 1);
        sIsLast = (c == gridDim.x - 1) ? 1 : 0;
    }
    __syncthreads();

    // ---- last block folds the final reduction (deterministic order) ----
    if (sIsLast) {
        float v = 0.0f;
        for (int i = tid; i < S_SIMS; i += BLOCK_THREADS) v += __ldcg(&g_partial[i]);
#pragma unroll
        for (int o = 16; o > 0; o >>= 1) v += __shfl_down_sync(0xffffffffu, v, o);
        if (lane == 0) sRedA[warp] = v;
        __syncthreads();
        if (tid == 0) {
            float tot = 0.0f;
#pragma unroll
            for (int w = 0; w < BLOCK_THREADS / 32; w++) tot += sRedA[w];
            out[0] = tot * (1.0f / ((float)T_LEN * (float)S_SIMS));
            g_count = 0;   // reset for next graph replay
        }
    }
}

extern "C" void kernel_launch(void* const* d_in, const int* in_sizes, int n_in,
                              void* d_out, int out_size) {
    const float* st  = (const float*)d_in[0];
    const float* at  = (const float*)d_in[1];
    const float* rw  = (const float*)d_in[2];
    const float* pW1 = (const float*)d_in[3];
    const float* pb1 = (const float*)d_in[4];
    const float* pW2 = (const float*)d_in[5];
    const float* pb2 = (const float*)d_in[6];
    const float* bW1 = (const float*)d_in[7];
    const float* bb1 = (const float*)d_in[8];
    const float* bW2 = (const float*)d_in[9];
    const float* bb2 = (const float*)d_in[10];
    const float* sd  = (const float*)d_in[11];
    float* out = (float*)d_out;

    mepg_main<<<S_SIMS, BLOCK_THREADS>>>(st, at, rw, pW1, pb1, pW2, pb2,
                                         bW1, bb1, bW2, bb2, sd, out);
}